// round 16
// baseline (speedup 1.0000x reference)
#include <cuda_runtime.h>
#include <cstdint>
#include <math.h>

#define DIMS   128
#define BINSZ  500
#define TILE_R 64
#define TILE_C 64
#define SPLITS 4
#define CPS    125      // cols per split (4*125 = 500)
#define MAXPTS 65536

// scratch (allocation-free rule: __device__ globals)
__device__ int   g_binid[MAXPTS];
__device__ float g_na[MAXPTS];
__device__ int   g_split[MAXPTS];
__device__ float g_sorted[(size_t)MAXPTS * DIMS];   // bin-sorted points copy
__device__ float g_nas[MAXPTS];                     // bin-sorted norms
__device__ float g_pk[MAXPTS * SPLITS * 5];
__device__ int   g_pj[MAXPTS * SPLITS * 5];

// ---------------------------------------------------------------------------
// K0: zero the 200MB output with wide stores (measured ~28.5us @ ~4.9TB/s).
// ---------------------------------------------------------------------------
__global__ void __launch_bounds__(256)
zero_kernel(float4* __restrict__ out, size_t n4)
{
    size_t stride = (size_t)gridDim.x * 256;
    float4 z = make_float4(0.f, 0.f, 0.f, 0.f);
    for (size_t i = (size_t)blockIdx.x * 256 + threadIdx.x; i < n4; i += stride)
        out[i] = z;
}

// ---------------------------------------------------------------------------
// K1: LSH projection -> bin id (first-max argmax) + squared norm.
// 8 threads per point (16 dims each) -> 313 blocks, better latency hiding.
// ---------------------------------------------------------------------------
__global__ void proj_kernel(const float* __restrict__ pts,
                            const float* __restrict__ rot,
                            int total, int nbins, int rotcols)
{
    const int nproj = nbins >> 1;                 // <= 8
    __shared__ float s_rot[8 * DIMS];
    for (int i = threadIdx.x; i < nproj * DIMS; i += blockDim.x) {
        int h = i >> 7, d = i & 127;
        s_rot[h * DIMS + d] = rot[d * rotcols + h];
    }
    __syncthreads();

    int p      = blockIdx.x * 32 + (threadIdx.x >> 3);
    int eighth = threadIdx.x & 7;

    float m[8];
    #pragma unroll
    for (int h = 0; h < 8; h++) m[h] = 0.f;
    float nrm = 0.f;

    if (p < total) {
        const float4* pv = (const float4*)(pts + (size_t)p * DIMS) + eighth * 4;
        #pragma unroll 4
        for (int d4 = 0; d4 < 4; d4++) {
            float4 v = pv[d4];
            nrm += v.x * v.x + v.y * v.y + v.z * v.z + v.w * v.w;
            int d0 = eighth * 16 + d4 * 4;
            for (int h = 0; h < nproj; h++) {
                const float* r = &s_rot[h * DIMS + d0];
                m[h] += v.x * r[0] + v.y * r[1] + v.z * r[2] + v.w * r[3];
            }
        }
    }
    for (int h = 0; h < nproj; h++) {
        m[h] += __shfl_xor_sync(0xffffffffu, m[h], 1);
        m[h] += __shfl_xor_sync(0xffffffffu, m[h], 2);
        m[h] += __shfl_xor_sync(0xffffffffu, m[h], 4);
    }
    nrm += __shfl_xor_sync(0xffffffffu, nrm, 1);
    nrm += __shfl_xor_sync(0xffffffffu, nrm, 2);
    nrm += __shfl_xor_sync(0xffffffffu, nrm, 4);

    if (eighth == 0 && p < total) {
        float best = m[0]; int bi = 0;
        for (int j = 1; j < nbins; j++) {
            float v = (j < nproj) ? m[j] : -m[j - nproj];
            if (v > best) { best = v; bi = j; }
        }
        g_binid[p] = bi;
        g_na[p]    = nrm;
    }
}

// ---------------------------------------------------------------------------
// K2: stable counting sort of bin ids per batch == jnp.argsort (stable).
// 1024 threads (chunk=5), dynamic smem: nbins*1024 counters + 33 aux.
// ---------------------------------------------------------------------------
__global__ void sort_kernel(int N, int nbins)
{
    extern __shared__ int s_cnt[];               // nbins*1024 + 33
    const int T = 1024;
    int* s_aux = s_cnt + nbins * T;
    int b   = blockIdx.x;
    int tid = threadIdx.x;

    int chunk = (N + T - 1) / T;
    int lo = tid * chunk; if (lo > N) lo = N;
    int hi = lo + chunk;  if (hi > N) hi = N;

    for (int bin = 0; bin < nbins; bin++) s_cnt[bin * T + tid] = 0;
    __syncthreads();
    for (int n = lo; n < hi; n++) s_cnt[g_binid[b * N + n] * T + tid]++;
    __syncthreads();

    int run = 0;
    int lane = tid & 31, warp = tid >> 5;        // 32 warps
    for (int bin = 0; bin < nbins; bin++) {
        int c = s_cnt[bin * T + tid];
        int x = c;
        #pragma unroll
        for (int o = 1; o < 32; o <<= 1) {
            int y = __shfl_up_sync(0xffffffffu, x, o);
            if (lane >= o) x += y;
        }
        if (lane == 31) s_aux[warp] = x;
        __syncthreads();
        if (warp == 0) {
            int w = s_aux[lane];
            #pragma unroll
            for (int o = 1; o < 32; o <<= 1) {
                int y = __shfl_up_sync(0xffffffffu, w, o);
                if (lane >= o) w += y;
            }
            s_aux[lane] = w;
        }
        __syncthreads();
        int base = (warp > 0) ? s_aux[warp - 1] : 0;
        int ex   = base + x - c;
        int tot  = s_aux[31];
        __syncthreads();
        s_cnt[bin * T + tid] = run + ex;
        run += tot;
        __syncthreads();
    }
    for (int n = lo; n < hi; n++) {
        int bin = g_binid[b * N + n];
        int pos = s_cnt[bin * T + tid]++;
        g_split[b * N + pos] = n;
    }
}

// ---------------------------------------------------------------------------
// K2b: gather points + norms into bin-sorted contiguous order (coalesced).
// ---------------------------------------------------------------------------
__global__ void __launch_bounds__(256)
gather_kernel(const float* __restrict__ pts, int N, int P)
{
    long t = (long)blockIdx.x * 256 + threadIdx.x;   // over P*32 float4s
    int row = (int)(t >> 5);
    int f4  = (int)(t & 31);
    if (row < P) {
        int b = row / N;
        int g = g_split[row];
        float4 v = ((const float4*)(pts + ((size_t)b * N + g) * DIMS))[f4];
        ((float4*)(g_sorted + (size_t)row * DIMS))[f4] = v;
        if (f4 == 0) g_nas[row] = g_na[b * N + g];
    }
}

// ---------------------------------------------------------------------------
// K3: per-(rowtile, colsplit) gram + bottom-5-of-d2 -> partial lists.
// grid = (8 rowtiles * 4 splits, nbins, B) = 640 blocks; block 256 = 8tx x 32ty.
// Thread tile 2 rows x 8 cols: selection regs halved vs 4x4 (natural alloc),
// 640 blocks x 8 warps -> ~24 resident warps/SM (3 blocks by smem).
// smem: na@0 (2KB) | rows@2048 (32KB) | cols@34816 (32KB); total 67584.
// merge overlay (post-compute): mk@2048 (10KB), mj@14336 (10KB).
// ---------------------------------------------------------------------------
__global__ void __launch_bounds__(256)
bin_kernel(int N, int nbins)
{
    extern __shared__ char sm[];
    float* s_na   = (float*)sm;
    float* s_rows = (float*)(sm + 2048);
    float* s_cols = (float*)(sm + 34816);
    float* s_mk   = (float*)(sm + 2048);
    int*   s_mj   = (int*)(sm + 14336);

    int bx    = blockIdx.x;
    int tile  = bx >> 2;
    int split = bx & 3;
    int bin   = blockIdx.y;
    int b     = blockIdx.z;
    int tid   = threadIdx.x;
    int tx = tid & 7, ty = tid >> 3;           // tx: 8 cols each, ty: 2 rows each

    const long binbase = (long)b * N + (long)bin * BINSZ;   // row offset in g_sorted

    for (int i = tid; i < BINSZ; i += 256)
        s_na[i] = g_nas[binbase + i];
    __syncthreads();

    // row tile: coalesced stream, 8 fixed iterations, transposed store
    int row0 = tile * TILE_R;
    #pragma unroll
    for (int it = 0; it < 8; it++) {
        int i  = tid + it * 256;               // 0..2047
        int r  = i & 63, d4 = i >> 6;
        float4 v = make_float4(0.f, 0.f, 0.f, 0.f);
        if (row0 + r < BINSZ)
            v = ((const float4*)(g_sorted + (binbase + row0 + r) * DIMS))[d4];
        s_rows[(d4 * 4 + 0) * TILE_R + r] = v.x;
        s_rows[(d4 * 4 + 1) * TILE_R + r] = v.y;
        s_rows[(d4 * 4 + 2) * TILE_R + r] = v.z;
        s_rows[(d4 * 4 + 3) * TILE_R + r] = v.w;
    }

    float na_row[2];
    float tk[2][5]; int tj[2][5];
    #pragma unroll
    for (int a = 0; a < 2; a++) {
        int grow = row0 + ty * 2 + a;
        na_row[a] = (grow < BINSZ) ? s_na[grow] : 0.f;
        #pragma unroll
        for (int q = 0; q < 5; q++) { tk[a][q] = 3.0e38f; tj[a][q] = 0x7fffffff; }
    }

    const int cbase = split * CPS;
    for (int c = 0; c < (CPS + TILE_C - 1) / TILE_C; c++) {   // 2 chunks: 64 + 61
        __syncthreads();
        int jb = c * TILE_C;
        #pragma unroll
        for (int it = 0; it < 8; it++) {
            int i  = tid + it * 256;
            int j  = i & 63, d4 = i >> 6;
            int jl = jb + j;
            float4 v = make_float4(0.f, 0.f, 0.f, 0.f);
            if (jl < CPS)
                v = ((const float4*)(g_sorted + (binbase + cbase + jl) * DIMS))[d4];
            s_cols[(d4 * 4 + 0) * TILE_C + j] = v.x;
            s_cols[(d4 * 4 + 1) * TILE_C + j] = v.y;
            s_cols[(d4 * 4 + 2) * TILE_C + j] = v.z;
            s_cols[(d4 * 4 + 3) * TILE_C + j] = v.w;
        }
        __syncthreads();

        float acc[2][8];
        #pragma unroll
        for (int a = 0; a < 2; a++)
            #pragma unroll
            for (int q = 0; q < 8; q++) acc[a][q] = 0.f;

        #pragma unroll 4
        for (int d = 0; d < DIMS; d++) {
            float2 rv  = *(const float2*)&s_rows[d * TILE_R + ty * 2];
            float4 cv0 = *(const float4*)&s_cols[d * TILE_C + tx * 8];
            float4 cv1 = *(const float4*)&s_cols[d * TILE_C + tx * 8 + 4];
            acc[0][0] += rv.x * cv0.x; acc[0][1] += rv.x * cv0.y;
            acc[0][2] += rv.x * cv0.z; acc[0][3] += rv.x * cv0.w;
            acc[0][4] += rv.x * cv1.x; acc[0][5] += rv.x * cv1.y;
            acc[0][6] += rv.x * cv1.z; acc[0][7] += rv.x * cv1.w;
            acc[1][0] += rv.y * cv0.x; acc[1][1] += rv.y * cv0.y;
            acc[1][2] += rv.y * cv0.z; acc[1][3] += rv.y * cv0.w;
            acc[1][4] += rv.y * cv1.x; acc[1][5] += rv.y * cv1.y;
            acc[1][6] += rv.y * cv1.z; acc[1][7] += rv.y * cv1.w;
        }

        // candidates: local j ascending per thread -> strict '<' keeps lowest idx
        #pragma unroll
        for (int q = 0; q < 8; q++) {
            int jl = jb + tx * 8 + q;
            if (jl < CPS) {
                float ncol = s_na[cbase + jl];
                #pragma unroll
                for (int a = 0; a < 2; a++) {
                    float key = fmaxf(na_row[a] - 2.f * acc[a][q] + ncol, 1e-6f);
                    if (key < tk[a][4]) {
                        tk[a][4] = key; tj[a][4] = jl;
                        #pragma unroll
                        for (int p = 4; p > 0; p--) {
                            if (tk[a][p] < tk[a][p - 1]) {
                                float kt = tk[a][p]; tk[a][p] = tk[a][p-1]; tk[a][p-1] = kt;
                                int   jt = tj[a][p]; tj[a][p] = tj[a][p-1]; tj[a][p-1] = jt;
                            }
                        }
                    }
                }
            }
        }
    }

    __syncthreads();   // compute done; overlay merge buffers
    #pragma unroll
    for (int a = 0; a < 2; a++) {
        int r = ty * 2 + a;
        int base = (r * 8 + tx) * 5;
        #pragma unroll
        for (int q = 0; q < 5; q++) { s_mk[base + q] = tk[a][q]; s_mj[base + q] = tj[a][q]; }
    }
    __syncthreads();

    if (tid < TILE_R) {
        int r = tid;
        int grow = row0 + r;
        if (grow < BINSZ) {
            float fk[5]; int fj[5];
            #pragma unroll
            for (int q = 0; q < 5; q++) { fk[q] = 3.0e38f; fj[q] = 0x7fffffff; }
            for (int t = 0; t < 8; t++) {
                int base = (r * 8 + t) * 5;
                #pragma unroll
                for (int q = 0; q < 5; q++) {
                    float key = s_mk[base + q]; int j = s_mj[base + q];
                    bool better = (key < fk[4]) || (key == fk[4] && j < fj[4]);
                    if (better) {
                        fk[4] = key; fj[4] = j;
                        #pragma unroll
                        for (int p = 4; p > 0; p--) {
                            bool sw = (fk[p] < fk[p-1]) ||
                                      (fk[p] == fk[p-1] && fj[p] < fj[p-1]);
                            if (sw) {
                                float kt = fk[p]; fk[p] = fk[p-1]; fk[p-1] = kt;
                                int   jt = fj[p]; fj[p] = fj[p-1]; fj[p-1] = jt;
                            }
                        }
                    }
                }
            }
            long base = (((long)(b * nbins + bin) * BINSZ + grow) * SPLITS + split) * 5;
            #pragma unroll
            for (int q = 0; q < 5; q++) {
                g_pk[base + q] = fk[q];
                g_pj[base + q] = cbase + fj[q];   // global index within bin
            }
        }
    }
}

// ---------------------------------------------------------------------------
// K4: merge 4 split lists per row ((key, j) order), eval exp(-0.1*sqrt(d2))
// on the 5 survivors, scatter into dense out.
// ---------------------------------------------------------------------------
__global__ void merge_kernel(float* __restrict__ out, int N, int nbins, int totalRows)
{
    int idx = blockIdx.x * 256 + threadIdx.x;
    if (idx >= totalRows) return;
    int b   = idx / N;
    int rem = idx - b * N;
    int bin = rem / BINSZ;
    int r   = rem - bin * BINSZ;

    long base = (long)idx * (SPLITS * 5);        // row-major layout matches bin_kernel

    float fk[5]; int fj[5];
    #pragma unroll
    for (int q = 0; q < 5; q++) { fk[q] = 3.0e38f; fj[q] = 0x7fffffff; }
    #pragma unroll
    for (int s = 0; s < SPLITS; s++) {
        #pragma unroll
        for (int q = 0; q < 5; q++) {
            float key = g_pk[base + s * 5 + q];
            int   j   = g_pj[base + s * 5 + q];
            bool better = (key < fk[4]) || (key == fk[4] && j < fj[4]);
            if (better) {
                fk[4] = key; fj[4] = j;
                #pragma unroll
                for (int p = 4; p > 0; p--) {
                    bool sw = (fk[p] < fk[p-1]) ||
                              (fk[p] == fk[p-1] && fj[p] < fj[p-1]);
                    if (sw) {
                        float kt = fk[p]; fk[p] = fk[p-1]; fk[p-1] = kt;
                        int   jt = fj[p]; fj[p] = fj[p-1]; fj[p-1] = jt;
                    }
                }
            }
        }
    }

    int src = g_split[b * N + bin * BINSZ + r];
    size_t rowbase = ((size_t)b * N + src) * (size_t)N;
    #pragma unroll
    for (int q = 0; q < 5; q++) {
        int dst = g_split[b * N + bin * BINSZ + fj[q]];
        out[rowbase + (size_t)dst] = expf(-0.1f * sqrtf(fk[q]));
    }
}

// ---------------------------------------------------------------------------
extern "C" void kernel_launch(void* const* d_in, const int* in_sizes, int n_in,
                              void* d_out, int out_size)
{
    const float* pts = (const float*)d_in[0];
    const float* rot = (const float*)d_in[1];

    int P       = in_sizes[0] / DIMS;              // B*N
    int rotcols = in_sizes[1] / DIMS;              // MAX_NUM_BINS/2
    int N       = (int)((long long)out_size / P);  // out = B*N*N
    int nbins   = N / BINSZ;
    int B       = P / N;

    cudaStream_t s2;
    cudaEvent_t  e1, e2;
    cudaStreamCreateWithFlags(&s2, cudaStreamNonBlocking);
    cudaEventCreateWithFlags(&e1, cudaEventDisableTiming);
    cudaEventCreateWithFlags(&e2, cudaEventDisableTiming);

    cudaEventRecord(e1, 0);
    cudaStreamWaitEvent(s2, e1, 0);

    int gatherBlocks = (int)(((long)P * 32 + 255) / 256);
    int sortSmem = nbins * 1024 * 4 + 33 * 4;
    cudaFuncSetAttribute(sort_kernel, cudaFuncAttributeMaxDynamicSharedMemorySize, sortSmem);

    proj_kernel<<<(P + 31) / 32, 256, 0, s2>>>(pts, rot, P, nbins, rotcols);   // 1
    sort_kernel<<<B, 1024, sortSmem, s2>>>(N, nbins);                          // 2
    gather_kernel<<<gatherBlocks, 256, 0, s2>>>(pts, N, P);                    // 3

    const int smem_bytes = 67584;
    cudaFuncSetAttribute(bin_kernel, cudaFuncAttributeMaxDynamicSharedMemorySize, smem_bytes);
    cudaFuncSetAttribute(bin_kernel, cudaFuncAttributePreferredSharedMemoryCarveout, 100);
    dim3 grid(((BINSZ + TILE_R - 1) / TILE_R) * SPLITS, nbins, B);
    bin_kernel<<<grid, 256, smem_bytes, s2>>>(N, nbins);                       // 4
    cudaEventRecord(e2, s2);

    // output zeroing on the main stream; no deps -> overlaps the whole chain
    size_t n4 = ((size_t)P * (size_t)N) / 4;
    zero_kernel<<<4096, 256>>>((float4*)d_out, n4);                            // 5

    cudaStreamWaitEvent(0, e2, 0);
    merge_kernel<<<(P + 255) / 256, 256>>>((float*)d_out, N, nbins, P);        // 6
}

// round 17
// speedup vs baseline: 1.1740x; 1.1740x over previous
#include <cuda_runtime.h>
#include <cstdint>
#include <math.h>

#define DIMS   128
#define BINSZ  500
#define NT     8                    // 64-row tiles per bin (ceil(500/64))
#define NPAIRS (NT * (NT + 1) / 2)  // 36 tile pairs (i <= j)
#define MAXPTS 65536

// scratch (allocation-free rule: __device__ globals)
__device__ int   g_binid[MAXPTS];
__device__ float g_na[MAXPTS];
__device__ int   g_split[MAXPTS];
__device__ float g_sorted[(size_t)MAXPTS * DIMS];   // bin-sorted points copy
__device__ float g_nas[MAXPTS];                     // bin-sorted norms
__device__ float g_pk[(size_t)MAXPTS * NT * 5];     // partial top-5 keys per (row, coltile)
__device__ int   g_pj[(size_t)MAXPTS * NT * 5];     // partial top-5 in-bin indices

// ---------------------------------------------------------------------------
// K0: zero the 200MB output with wide stores (measured ~28.5us @ ~4.9TB/s).
// ---------------------------------------------------------------------------
__global__ void __launch_bounds__(256)
zero_kernel(float4* __restrict__ out, size_t n4)
{
    size_t stride = (size_t)gridDim.x * 256;
    float4 z = make_float4(0.f, 0.f, 0.f, 0.f);
    for (size_t i = (size_t)blockIdx.x * 256 + threadIdx.x; i < n4; i += stride)
        out[i] = z;
}

// ---------------------------------------------------------------------------
// K1: LSH projection -> bin id (first-max argmax) + squared norm.
// (R14 bit-exact version: 4 threads/point.)
// ---------------------------------------------------------------------------
__global__ void proj_kernel(const float* __restrict__ pts,
                            const float* __restrict__ rot,
                            int total, int nbins, int rotcols)
{
    const int nproj = nbins >> 1;                 // <= 8
    __shared__ float s_rot[8 * DIMS];
    for (int i = threadIdx.x; i < nproj * DIMS; i += blockDim.x) {
        int h = i >> 7, d = i & 127;
        s_rot[h * DIMS + d] = rot[d * rotcols + h];
    }
    __syncthreads();

    int p       = blockIdx.x * 64 + (threadIdx.x >> 2);
    int quarter = threadIdx.x & 3;

    float m[8];
    #pragma unroll
    for (int h = 0; h < 8; h++) m[h] = 0.f;
    float nrm = 0.f;

    if (p < total) {
        const float4* pv = (const float4*)(pts + (size_t)p * DIMS) + quarter * 8;
        #pragma unroll 8
        for (int d4 = 0; d4 < 8; d4++) {
            float4 v = pv[d4];
            nrm += v.x * v.x + v.y * v.y + v.z * v.z + v.w * v.w;
            int d0 = quarter * 32 + d4 * 4;
            for (int h = 0; h < nproj; h++) {
                const float* r = &s_rot[h * DIMS + d0];
                m[h] += v.x * r[0] + v.y * r[1] + v.z * r[2] + v.w * r[3];
            }
        }
    }
    for (int h = 0; h < nproj; h++) {
        m[h] += __shfl_xor_sync(0xffffffffu, m[h], 1);
        m[h] += __shfl_xor_sync(0xffffffffu, m[h], 2);
    }
    nrm += __shfl_xor_sync(0xffffffffu, nrm, 1);
    nrm += __shfl_xor_sync(0xffffffffu, nrm, 2);

    if (quarter == 0 && p < total) {
        float best = m[0]; int bi = 0;
        for (int j = 1; j < nbins; j++) {
            float v = (j < nproj) ? m[j] : -m[j - nproj];
            if (v > best) { best = v; bi = j; }
        }
        g_binid[p] = bi;
        g_na[p]    = nrm;
    }
}

// ---------------------------------------------------------------------------
// K2: stable counting sort of bin ids per batch == jnp.argsort (stable).
// 1024 threads; order-equivalent to any chunk size (stable by construction).
// ---------------------------------------------------------------------------
__global__ void sort_kernel(int N, int nbins)
{
    extern __shared__ int s_cnt[];               // nbins*1024 + 33
    const int T = 1024;
    int* s_aux = s_cnt + nbins * T;
    int b   = blockIdx.x;
    int tid = threadIdx.x;

    int chunk = (N + T - 1) / T;
    int lo = tid * chunk; if (lo > N) lo = N;
    int hi = lo + chunk;  if (hi > N) hi = N;

    for (int bin = 0; bin < nbins; bin++) s_cnt[bin * T + tid] = 0;
    __syncthreads();
    for (int n = lo; n < hi; n++) s_cnt[g_binid[b * N + n] * T + tid]++;
    __syncthreads();

    int run = 0;
    int lane = tid & 31, warp = tid >> 5;        // 32 warps
    for (int bin = 0; bin < nbins; bin++) {
        int c = s_cnt[bin * T + tid];
        int x = c;
        #pragma unroll
        for (int o = 1; o < 32; o <<= 1) {
            int y = __shfl_up_sync(0xffffffffu, x, o);
            if (lane >= o) x += y;
        }
        if (lane == 31) s_aux[warp] = x;
        __syncthreads();
        if (warp == 0) {
            int w = s_aux[lane];
            #pragma unroll
            for (int o = 1; o < 32; o <<= 1) {
                int y = __shfl_up_sync(0xffffffffu, w, o);
                if (lane >= o) w += y;
            }
            s_aux[lane] = w;
        }
        __syncthreads();
        int base = (warp > 0) ? s_aux[warp - 1] : 0;
        int ex   = base + x - c;
        int tot  = s_aux[31];
        __syncthreads();
        s_cnt[bin * T + tid] = run + ex;
        run += tot;
        __syncthreads();
    }
    for (int n = lo; n < hi; n++) {
        int bin = g_binid[b * N + n];
        int pos = s_cnt[bin * T + tid]++;
        g_split[b * N + pos] = n;
    }
}

// ---------------------------------------------------------------------------
// K2b: gather points + norms into bin-sorted contiguous order (coalesced).
// ---------------------------------------------------------------------------
__global__ void __launch_bounds__(256)
gather_kernel(const float* __restrict__ pts, int N, int P)
{
    long t = (long)blockIdx.x * 256 + threadIdx.x;   // over P*32 float4s
    int row = (int)(t >> 5);
    int f4  = (int)(t & 31);
    if (row < P) {
        int b = row / N;
        int g = g_split[row];
        float4 v = ((const float4*)(pts + ((size_t)b * N + g) * DIMS))[f4];
        ((float4*)(g_sorted + (size_t)row * DIMS))[f4] = v;
        if (f4 == 0) g_nas[row] = g_na[b * N + g];
    }
}

// ---------------------------------------------------------------------------
// K3: SYMMETRIC tile-pair gram + bottom-5-of-d2.
// grid = (36 pairs, nbins, B) = 720 blocks; block 256 = 16(tx) x 16(ty),
// thread tile 4x4 (the proven shape). Block (i,j), i<=j, computes the 64x64
// tile rows(i) x cols(j) ONCE; emits row-side lists (slot j) and, if i!=j,
// col-side lists (slot i). ~0.59x FLOPs+LDS of the full gram.
// smem: na@0 (2KB) | rows@2048 (32KB) | cols@34816 (32KB); total 67584.
// epilogue overlay: mk@2048 (20KB), mj@22528 (20KB).
// ---------------------------------------------------------------------------
__global__ void __launch_bounds__(256)
bin_kernel(int N, int nbins)
{
    extern __shared__ char sm[];
    float* s_na   = (float*)sm;
    float* s_rows = (float*)(sm + 2048);
    float* s_cols = (float*)(sm + 34816);
    float* s_mk   = (float*)(sm + 2048);
    int*   s_mj   = (int*)(sm + 22528);

    int bin = blockIdx.y;
    int b   = blockIdx.z;
    int tid = threadIdx.x;
    int tx = tid & 15, ty = tid >> 4;

    // map pair index -> (it, jt), it <= jt
    int it = 0, rem = blockIdx.x;
    while (rem >= NT - it) { rem -= NT - it; it++; }
    int jt = it + rem;

    const long binbase = (long)b * N + (long)bin * BINSZ;

    for (int i = tid; i < BINSZ; i += 256)
        s_na[i] = g_nas[binbase + i];

    int row0 = it * 64, col0 = jt * 64;

    // load row tile (transposed, d-major), coalesced, fixed 8 iterations
    #pragma unroll
    for (int k = 0; k < 8; k++) {
        int i = tid + k * 256;
        int r = i & 63, d4 = i >> 6;
        float4 v = make_float4(0.f, 0.f, 0.f, 0.f);
        if (row0 + r < BINSZ)
            v = ((const float4*)(g_sorted + (binbase + row0 + r) * DIMS))[d4];
        s_rows[(d4 * 4 + 0) * 64 + r] = v.x;
        s_rows[(d4 * 4 + 1) * 64 + r] = v.y;
        s_rows[(d4 * 4 + 2) * 64 + r] = v.z;
        s_rows[(d4 * 4 + 3) * 64 + r] = v.w;
    }
    // load col tile
    #pragma unroll
    for (int k = 0; k < 8; k++) {
        int i = tid + k * 256;
        int r = i & 63, d4 = i >> 6;
        float4 v = make_float4(0.f, 0.f, 0.f, 0.f);
        if (col0 + r < BINSZ)
            v = ((const float4*)(g_sorted + (binbase + col0 + r) * DIMS))[d4];
        s_cols[(d4 * 4 + 0) * 64 + r] = v.x;
        s_cols[(d4 * 4 + 1) * 64 + r] = v.y;
        s_cols[(d4 * 4 + 2) * 64 + r] = v.z;
        s_cols[(d4 * 4 + 3) * 64 + r] = v.w;
    }
    __syncthreads();

    float acc[4][4];
    #pragma unroll
    for (int a = 0; a < 4; a++)
        #pragma unroll
        for (int q = 0; q < 4; q++) acc[a][q] = 0.f;

    #pragma unroll 4
    for (int d = 0; d < DIMS; d++) {
        float4 rv = *(const float4*)&s_rows[d * 64 + ty * 4];
        float4 cv = *(const float4*)&s_cols[d * 64 + tx * 4];
        acc[0][0] += rv.x * cv.x; acc[0][1] += rv.x * cv.y;
        acc[0][2] += rv.x * cv.z; acc[0][3] += rv.x * cv.w;
        acc[1][0] += rv.y * cv.x; acc[1][1] += rv.y * cv.y;
        acc[1][2] += rv.y * cv.z; acc[1][3] += rv.y * cv.w;
        acc[2][0] += rv.z * cv.x; acc[2][1] += rv.z * cv.y;
        acc[2][2] += rv.z * cv.z; acc[2][3] += rv.z * cv.w;
        acc[3][0] += rv.w * cv.x; acc[3][1] += rv.w * cv.y;
        acc[3][2] += rv.w * cv.z; acc[3][3] += rv.w * cv.w;
    }

    float na_row[4], na_col[4];
    #pragma unroll
    for (int a = 0; a < 4; a++) {
        int r = row0 + ty * 4 + a;
        na_row[a] = (r < BINSZ) ? s_na[r] : 0.f;
    }
    #pragma unroll
    for (int q = 0; q < 4; q++) {
        int c = col0 + tx * 4 + q;
        na_col[q] = (c < BINSZ) ? s_na[c] : 0.f;
    }

    // ---- row side: per-thread top5 over my 4 cols, for each of my 4 rows ----
    __syncthreads();   // mainloop reads done; overlay begins
    #pragma unroll
    for (int a = 0; a < 4; a++) {
        float rk[5]; int rj[5];
        #pragma unroll
        for (int q = 0; q < 5; q++) { rk[q] = 3.0e38f; rj[q] = 0x7fffffff; }
        #pragma unroll
        for (int q = 0; q < 4; q++) {          // j ascending -> strict '<' tie rule
            int jl = col0 + tx * 4 + q;
            if (jl < BINSZ) {
                float key = fmaxf(na_row[a] - 2.f * acc[a][q] + na_col[q], 1e-6f);
                if (key < rk[4]) {
                    rk[4] = key; rj[4] = jl;
                    #pragma unroll
                    for (int p = 4; p > 0; p--) {
                        if (rk[p] < rk[p - 1]) {
                            float kt = rk[p]; rk[p] = rk[p-1]; rk[p-1] = kt;
                            int   jt2 = rj[p]; rj[p] = rj[p-1]; rj[p-1] = jt2;
                        }
                    }
                }
            }
        }
        int base = ((ty * 4 + a) * 16 + tx) * 5;
        #pragma unroll
        for (int q = 0; q < 5; q++) { s_mk[base + q] = rk[q]; s_mj[base + q] = rj[q]; }
    }
    __syncthreads();
    if (tid < 64 && row0 + tid < BINSZ) {
        float fk[5]; int fj[5];
        #pragma unroll
        for (int q = 0; q < 5; q++) { fk[q] = 3.0e38f; fj[q] = 0x7fffffff; }
        for (int t = 0; t < 16; t++) {
            int base = (tid * 16 + t) * 5;
            #pragma unroll
            for (int q = 0; q < 5; q++) {
                float key = s_mk[base + q]; int j = s_mj[base + q];
                bool better = (key < fk[4]) || (key == fk[4] && j < fj[4]);
                if (better) {
                    fk[4] = key; fj[4] = j;
                    #pragma unroll
                    for (int p = 4; p > 0; p--) {
                        bool sw = (fk[p] < fk[p-1]) ||
                                  (fk[p] == fk[p-1] && fj[p] < fj[p-1]);
                        if (sw) {
                            float kt = fk[p]; fk[p] = fk[p-1]; fk[p-1] = kt;
                            int   jt2 = fj[p]; fj[p] = fj[p-1]; fj[p-1] = jt2;
                        }
                    }
                }
            }
        }
        long ob = ((binbase + row0 + tid) * NT + jt) * 5;
        #pragma unroll
        for (int q = 0; q < 5; q++) { g_pk[ob + q] = fk[q]; g_pj[ob + q] = fj[q]; }
    }

    // ---- col side (transposed), only off-diagonal blocks ----
    if (it != jt) {
        __syncthreads();
        #pragma unroll
        for (int q = 0; q < 4; q++) {
            float ck[5]; int cj[5];
            #pragma unroll
            for (int p = 0; p < 5; p++) { ck[p] = 3.0e38f; cj[p] = 0x7fffffff; }
            #pragma unroll
            for (int a = 0; a < 4; a++) {      // j ascending (rows of tile i)
                int jl = row0 + ty * 4 + a;
                if (jl < BINSZ) {
                    float key = fmaxf(na_col[q] - 2.f * acc[a][q] + na_row[a], 1e-6f);
                    if (key < ck[4]) {
                        ck[4] = key; cj[4] = jl;
                        #pragma unroll
                        for (int p = 4; p > 0; p--) {
                            if (ck[p] < ck[p - 1]) {
                                float kt = ck[p]; ck[p] = ck[p-1]; ck[p-1] = kt;
                                int   jt2 = cj[p]; cj[p] = cj[p-1]; cj[p-1] = jt2;
                            }
                        }
                    }
                }
            }
            int base = ((tx * 4 + q) * 16 + ty) * 5;
            #pragma unroll
            for (int p = 0; p < 5; p++) { s_mk[base + p] = ck[p]; s_mj[base + p] = cj[p]; }
        }
        __syncthreads();
        if (tid < 64 && col0 + tid < BINSZ) {
            float fk[5]; int fj[5];
            #pragma unroll
            for (int q = 0; q < 5; q++) { fk[q] = 3.0e38f; fj[q] = 0x7fffffff; }
            for (int t = 0; t < 16; t++) {
                int base = (tid * 16 + t) * 5;
                #pragma unroll
                for (int q = 0; q < 5; q++) {
                    float key = s_mk[base + q]; int j = s_mj[base + q];
                    bool better = (key < fk[4]) || (key == fk[4] && j < fj[4]);
                    if (better) {
                        fk[4] = key; fj[4] = j;
                        #pragma unroll
                        for (int p = 4; p > 0; p--) {
                            bool sw = (fk[p] < fk[p-1]) ||
                                      (fk[p] == fk[p-1] && fj[p] < fj[p-1]);
                            if (sw) {
                                float kt = fk[p]; fk[p] = fk[p-1]; fk[p-1] = kt;
                                int   jt2 = fj[p]; fj[p] = fj[p-1]; fj[p-1] = jt2;
                            }
                        }
                    }
                }
            }
            long ob = ((binbase + col0 + tid) * NT + it) * 5;
            #pragma unroll
            for (int q = 0; q < 5; q++) { g_pk[ob + q] = fk[q]; g_pj[ob + q] = fj[q]; }
        }
    }
}

// ---------------------------------------------------------------------------
// K4: merge NT=8 partial lists per row ((key, j) order), eval exp(-0.1*sqrt)
// on the 5 survivors, scatter into dense out. Vectorized float4/int4 reads.
// ---------------------------------------------------------------------------
__global__ void merge_kernel(float* __restrict__ out, int N, int nbins, int totalRows)
{
    int idx = blockIdx.x * 256 + threadIdx.x;
    if (idx >= totalRows) return;
    int b   = idx / N;
    int rem = idx - b * N;
    int bin = rem / BINSZ;
    int r   = rem - bin * BINSZ;

    long base = (long)idx * (NT * 5);            // 40 entries, 16B-aligned
    float lk[NT * 5]; int lj[NT * 5];
    const float4* pk4 = (const float4*)(g_pk + base);
    const int4*   pj4 = (const int4*)(g_pj + base);
    #pragma unroll
    for (int v = 0; v < NT * 5 / 4; v++) {
        ((float4*)lk)[v] = pk4[v];
        ((int4*)lj)[v]   = pj4[v];
    }

    float fk[5]; int fj[5];
    #pragma unroll
    for (int q = 0; q < 5; q++) { fk[q] = 3.0e38f; fj[q] = 0x7fffffff; }
    #pragma unroll
    for (int s = 0; s < NT * 5; s++) {
        float key = lk[s]; int j = lj[s];
        bool better = (key < fk[4]) || (key == fk[4] && j < fj[4]);
        if (better) {
            fk[4] = key; fj[4] = j;
            #pragma unroll
            for (int p = 4; p > 0; p--) {
                bool sw = (fk[p] < fk[p-1]) ||
                          (fk[p] == fk[p-1] && fj[p] < fj[p-1]);
                if (sw) {
                    float kt = fk[p]; fk[p] = fk[p-1]; fk[p-1] = kt;
                    int   jt = fj[p]; fj[p] = fj[p-1]; fj[p-1] = jt;
                }
            }
        }
    }

    int src = g_split[idx];
    size_t rowbase = ((size_t)b * N + src) * (size_t)N;
    #pragma unroll
    for (int q = 0; q < 5; q++) {
        int dst = g_split[b * N + bin * BINSZ + fj[q]];
        out[rowbase + (size_t)dst] = expf(-0.1f * sqrtf(fk[q]));
    }
}

// ---------------------------------------------------------------------------
extern "C" void kernel_launch(void* const* d_in, const int* in_sizes, int n_in,
                              void* d_out, int out_size)
{
    const float* pts = (const float*)d_in[0];
    const float* rot = (const float*)d_in[1];

    int P       = in_sizes[0] / DIMS;              // B*N
    int rotcols = in_sizes[1] / DIMS;              // MAX_NUM_BINS/2
    int N       = (int)((long long)out_size / P);  // out = B*N*N
    int nbins   = N / BINSZ;
    int B       = P / N;

    cudaStream_t s2;
    cudaEvent_t  e1, e2;
    cudaStreamCreateWithFlags(&s2, cudaStreamNonBlocking);
    cudaEventCreateWithFlags(&e1, cudaEventDisableTiming);
    cudaEventCreateWithFlags(&e2, cudaEventDisableTiming);

    cudaEventRecord(e1, 0);
    cudaStreamWaitEvent(s2, e1, 0);

    int gatherBlocks = (int)(((long)P * 32 + 255) / 256);
    int sortSmem = nbins * 1024 * 4 + 33 * 4;
    cudaFuncSetAttribute(sort_kernel, cudaFuncAttributeMaxDynamicSharedMemorySize, sortSmem);

    proj_kernel<<<(P + 63) / 64, 256, 0, s2>>>(pts, rot, P, nbins, rotcols);   // 1
    sort_kernel<<<B, 1024, sortSmem, s2>>>(N, nbins);                          // 2
    gather_kernel<<<gatherBlocks, 256, 0, s2>>>(pts, N, P);                    // 3

    const int smem_bytes = 67584;
    cudaFuncSetAttribute(bin_kernel, cudaFuncAttributeMaxDynamicSharedMemorySize, smem_bytes);
    cudaFuncSetAttribute(bin_kernel, cudaFuncAttributePreferredSharedMemoryCarveout, 100);
    dim3 grid(NPAIRS, nbins, B);
    bin_kernel<<<grid, 256, smem_bytes, s2>>>(N, nbins);                       // 4
    cudaEventRecord(e2, s2);

    // output zeroing on the main stream; no deps -> overlaps the whole chain
    size_t n4 = ((size_t)P * (size_t)N) / 4;
    zero_kernel<<<4096, 256>>>((float4*)d_out, n4);                            // 5

    cudaStreamWaitEvent(0, e2, 0);
    merge_kernel<<<(P + 255) / 256, 256>>>((float*)d_out, N, nbins, P);        // 6
}